// round 17
// baseline (speedup 1.0000x reference)
#include <cuda_runtime.h>

#define Bn   32
#define Nn   1024
#define MLc  3
#define HIDn 100
#define ODIM 147
#define CK   13
#define WP   16            // padded weight-row stride
#define WPAD (CK * WP)     // 208

// interior tile: 64 rows x 128 cols, block = 256 threads (8 warps)
#define TH_  64
#define TW_  128
#define IRH  76    // TH_ + 12
#define IRW  140   // TW_ + 12
#define SRP  140   // sr pitch (rows 16B-aligned: 140*4=560)

// dynamic smem layout (float offsets)
#define OFF_SR   0
#define OFF_SW   (IRH * SRP)          // 10640 (x4 = 42560, 16B aligned)
#define SMEM_FLOATS (OFF_SW + WPAD)   // 10848
#define SMEM_BYTES  (SMEM_FLOATS * 4) // 43392

// frame-path offsets (same buffer; max 8449 < 10848)
#define FOFF_SX  0
#define FOFF_SR  2416
#define FOFF_ST  4520
#define FOFF_W1  8140
#define FOFF_W2  8290
#define FOFF_KA  8440

#define NBX  8               // tiles across (128-wide)
#define NBY  16              // tiles down (64-tall)
#define NINT (NBX * NBY)     // 128 interior blocks

__device__ float g_w1[Bn][ODIM];
__device__ float g_w2[Bn][ODIM];
__device__ float g_W13p[Bn][WPAD];

// ---------------------------------------------------------------------------
// Kernel 0: both MLPs (ILP-10 layer 2) + composite 13x13 (padded). 768 thr.
// ---------------------------------------------------------------------------
__global__ __launch_bounds__(768)
void mlp_kernel(const float* __restrict__ kA,
                const float* __restrict__ w1a, const float* __restrict__ b1a,
                const float* __restrict__ w2a, const float* __restrict__ b2a,
                const float* __restrict__ w1b, const float* __restrict__ b1b,
                const float* __restrict__ w2b, const float* __restrict__ b2b) {
    const int b = blockIdx.x;
    const int t = threadIdx.x;
    const int path = t / 384;
    const int s = t - path * 384;
    __shared__ float skA[9];
    __shared__ float h[2][HIDn];
    __shared__ float part[2][ODIM][2];
    __shared__ float sh1[ODIM];
    __shared__ float sh2[ODIM];

    if (t < 9) skA[t] = kA[b * 9 + t];
    __syncthreads();

    const float* W1 = path ? w1b : w1a;
    const float* B1 = path ? b1b : b1a;
    const float* W2 = path ? w2b : w2a;
    const float* B2 = path ? b2b : b2a;

    if (s < HIDn) {
        float acc = B1[s];
#pragma unroll
        for (int k = 0; k < 9; k++) acc += skA[k] * W1[k * HIDn + s];
        h[path][s] = fmaxf(acc, 0.f);
    }
    __syncthreads();

    {
        const int o = s >> 1, half = s & 1;
        if (o < ODIM) {
            const int k0 = half * 50;
            float a[10];
#pragma unroll
            for (int j = 0; j < 10; j++) a[j] = 0.f;
#pragma unroll
            for (int kk = 0; kk < 5; kk++)
#pragma unroll
                for (int j = 0; j < 10; j++)
                    a[j] += h[path][k0 + kk * 10 + j] * W2[(k0 + kk * 10 + j) * ODIM + o];
            float acc = (((a[0] + a[1]) + (a[2] + a[3])) + ((a[4] + a[5]) + (a[6] + a[7]))) + (a[8] + a[9]);
            if (half == 0) acc += B2[o];
            part[path][o][half] = acc;
        }
    }
    __syncthreads();

    if (t < 2 * ODIM) {
        int pp = t / ODIM, o = t - pp * ODIM;
        float acc = part[pp][o][0] + part[pp][o][1];
        if (pp) { sh2[o] = acc; g_w2[b][o] = acc; }
        else    { sh1[o] = acc; g_w1[b][o] = acc; }
    }
    __syncthreads();

    if (t < WPAD) {
        int u = t >> 4, v = t & 15;
        float acc = 0.f;
        if (v < CK) {
            int i0 = max(0, u - 6), i1 = min(6, u);
            int j0 = max(0, v - 6), j1 = min(6, v);
            for (int m = 0; m < MLc; m++)
                for (int i = i0; i <= i1; i++)
                    for (int j = j0; j <= j1; j++)
                        acc += sh2[m * 49 + i * 7 + j] * sh1[m * 49 + (u - i) * 7 + (v - j)];
        }
        g_W13p[b][t] = acc;
    }
}

// apply one 13-tap weight row (padded base wp) to acc[4] using rv[0..15]
__device__ __forceinline__ void apply_row4(const float* __restrict__ wp,
                                           const float rv[16], float acc[4]) {
    const float4* wq = reinterpret_cast<const float4*>(wp);
    float4 wa = wq[0];
#pragma unroll
    for (int k = 0; k < 4; k++) acc[k] = fmaf(wa.x, rv[0 + k], acc[k]);
#pragma unroll
    for (int k = 0; k < 4; k++) acc[k] = fmaf(wa.y, rv[1 + k], acc[k]);
#pragma unroll
    for (int k = 0; k < 4; k++) acc[k] = fmaf(wa.z, rv[2 + k], acc[k]);
#pragma unroll
    for (int k = 0; k < 4; k++) acc[k] = fmaf(wa.w, rv[3 + k], acc[k]);
    float4 wb = wq[1];
#pragma unroll
    for (int k = 0; k < 4; k++) acc[k] = fmaf(wb.x, rv[4 + k], acc[k]);
#pragma unroll
    for (int k = 0; k < 4; k++) acc[k] = fmaf(wb.y, rv[5 + k], acc[k]);
#pragma unroll
    for (int k = 0; k < 4; k++) acc[k] = fmaf(wb.z, rv[6 + k], acc[k]);
#pragma unroll
    for (int k = 0; k < 4; k++) acc[k] = fmaf(wb.w, rv[7 + k], acc[k]);
    float4 wc = wq[2];
#pragma unroll
    for (int k = 0; k < 4; k++) acc[k] = fmaf(wc.x, rv[8 + k], acc[k]);
#pragma unroll
    for (int k = 0; k < 4; k++) acc[k] = fmaf(wc.y, rv[9 + k], acc[k]);
#pragma unroll
    for (int k = 0; k < 4; k++) acc[k] = fmaf(wc.z, rv[10 + k], acc[k]);
#pragma unroll
    for (int k = 0; k < 4; k++) acc[k] = fmaf(wc.w, rv[11 + k], acc[k]);
    float w12 = wp[12];
#pragma unroll
    for (int k = 0; k < 4; k++) acc[k] = fmaf(w12, rv[12 + k], acc[k]);
}

__device__ __forceinline__ void load_rv16(const float* __restrict__ p, float rv[16]) {
    const float4* q = reinterpret_cast<const float4*>(p);
#pragma unroll
    for (int m = 0; m < 4; m++) {
        float4 t = q[m];
        rv[4 * m + 0] = t.x; rv[4 * m + 1] = t.y;
        rv[4 * m + 2] = t.z; rv[4 * m + 3] = t.w;
    }
}

// ---------------------------------------------------------------------------
// Fused kernel. grid (160, Bn), block 256, dynamic smem 43.4 KB, 3 blocks/SM.
// blockIdx.x < 128 -> interior 64x128 tile; else frame segment.
// ---------------------------------------------------------------------------
__global__ __launch_bounds__(256, 3)
void fused_kernel(const float* __restrict__ x, const float* __restrict__ f,
                  const float* __restrict__ kA, float* __restrict__ out) {
    extern __shared__ __align__(16) float smem[];
    const int b   = blockIdx.y;
    const int tid = threadIdx.x;
    const int lane = tid & 31;
    const int wid  = tid >> 5;          // 0..7

    const float* xb = x + (size_t)b * Nn * Nn;
    const float* fb = f + (size_t)b * Nn * Nn;
    float*       ob = out + (size_t)b * Nn * Nn;

    if (blockIdx.x < NINT) {
        // ================= interior path =================
        const int bx = blockIdx.x & (NBX - 1), by = blockIdx.x >> 3;
        const int ty0 = by * TH_, tx0 = bx * TW_;
        const bool edge = (bx == 0) | (bx == NBX - 1) | (by == 0) | (by == NBY - 1);

        float* sr = smem + OFF_SR;
        float* sW = smem + OFF_SW;
        __shared__ float skA[9];

        if (tid < WPAD) sW[tid] = g_W13p[b][tid];
        if (tid < 9) skA[tid] = kA[b * 9 + tid];
        __syncthreads();

        float k0 = skA[0], k1 = skA[1], k2 = skA[2],
              k3 = skA[3], k4 = skA[4], k5 = skA[5],
              k6 = skA[6], k7 = skA[7], k8 = skA[8];

        if (!edge) {
            // Stage B: r rows in pairs, x via LDG, no bounds checks.
#pragma unroll 1
            for (int u2 = wid; u2 < IRH / 2; u2 += 8) {
                const int gy = ty0 - 6 + 2 * u2;
                float* r0p = &sr[(2 * u2) * SRP];
                float* r1p = &sr[(2 * u2 + 1) * SRP];
                const float* xrow = &xb[(size_t)(gy - 1) * Nn + tx0 - 6];
                const float* f0 = &fb[(size_t)gy * Nn + tx0 - 6];
                const float* f1 = f0 + Nn;
#pragma unroll 1
                for (int v = lane; v < IRW; v += 32) {
                    const float* xp = xrow + v;
                    float a0 = __ldg(xp - 1),        a1 = __ldg(xp),        a2 = __ldg(xp + 1);
                    float b0 = __ldg(xp + Nn - 1),   b1 = __ldg(xp + Nn),   b2 = __ldg(xp + Nn + 1);
                    float c0 = __ldg(xp + 2*Nn - 1), c1 = __ldg(xp + 2*Nn), c2 = __ldg(xp + 2*Nn + 1);
                    float d0 = __ldg(xp + 3*Nn - 1), d1 = __ldg(xp + 3*Nn), d2 = __ldg(xp + 3*Nn + 1);
                    float r0 = f0[v];
                    r0 -= k0 * a0; r0 -= k1 * a1; r0 -= k2 * a2;
                    r0 -= k3 * b0; r0 -= k4 * b1; r0 -= k5 * b2;
                    r0 -= k6 * c0; r0 -= k7 * c1; r0 -= k8 * c2;
                    float r1 = f1[v];
                    r1 -= k0 * b0; r1 -= k1 * b1; r1 -= k2 * b2;
                    r1 -= k3 * c0; r1 -= k4 * c1; r1 -= k5 * c2;
                    r1 -= k6 * d0; r1 -= k7 * d1; r1 -= k8 * d2;
                    r0p[v] = r0;
                    r1p[v] = r1;
                }
            }
        } else {
            // edge: per-row, per-tap bounds-checked LDG (zero-pad)
#pragma unroll 1
            for (int u = wid; u < IRH; u += 8) {
                const int gy = ty0 - 6 + u;
                float* sp = &sr[u * SRP];
                const bool rok = (gy >= 0 && gy < Nn);
#pragma unroll 1
                for (int v = lane; v < IRW; v += 32) {
                    const int gx = tx0 - 6 + v;
                    float val = 0.f;
                    if (rok && gx >= 0 && gx < Nn) {
                        float acc = fb[(size_t)gy * Nn + gx];
#pragma unroll
                        for (int dr = -1; dr <= 1; dr++) {
                            int ty = gy + dr;
                            if (ty < 0 || ty >= Nn) continue;
#pragma unroll
                            for (int dc = -1; dc <= 1; dc++) {
                                int tx2 = gx + dc;
                                if (tx2 < 0 || tx2 >= Nn) continue;
                                float kv = skA[(dr + 1) * 3 + (dc + 1)];
                                acc -= kv * xb[(size_t)ty * Nn + tx2];
                            }
                        }
                        val = acc;
                    }
                    sp[v] = val;
                }
            }
        }
        __syncthreads();

        // Stage C: sliding window. warp = 8-row output group, lane = 4-px strip.
        // Out rows ty0+8*wid+y (y 0..7), cols tx0+4*lane..+3.
        // r local rows 8*wid + jj (jj 0..19); row jj applies weight row (jj-y)
        // to acc[y] when 0 <= jj-y <= 12 (compile-time under full unroll).
        const int v0 = lane << 2;
        float acc[8][4];
#pragma unroll
        for (int y = 0; y < 8; y++)
#pragma unroll
            for (int k = 0; k < 4; k++) acc[y][k] = 0.f;

        const float* rbase = &sr[(8 * wid) * SRP + v0];
        float rv[16];
#pragma unroll
        for (int jj = 0; jj < 20; jj++) {
            load_rv16(rbase + jj * SRP, rv);
#pragma unroll
            for (int y = 0; y < 8; y++) {
                if (jj - y >= 0 && jj - y <= 12)
                    apply_row4(&sW[(jj - y) * WP], rv, acc[y]);
            }
        }

        // store: out = x + G2 (lanes = contiguous 512B row segments)
        const int gx0 = tx0 + v0;
        if (!edge) {
#pragma unroll
            for (int y = 0; y < 8; y++) {
                const int gy = ty0 + 8 * wid + y;
                const float4 xv = *reinterpret_cast<const float4*>(&xb[(size_t)gy * Nn + gx0]);
                float4 q;
                q.x = acc[y][0] + xv.x; q.y = acc[y][1] + xv.y;
                q.z = acc[y][2] + xv.z; q.w = acc[y][3] + xv.w;
                *reinterpret_cast<float4*>(&ob[(size_t)gy * Nn + gx0]) = q;
            }
        } else {
#pragma unroll
            for (int y = 0; y < 8; y++) {
                const int gy = ty0 + 8 * wid + y;
                if (gy < 3 || gy >= Nn - 3) continue;
#pragma unroll
                for (int k = 0; k < 4; k++) {
                    const int gx = gx0 + k;
                    if (gx >= 3 && gx < Nn - 3)
                        ob[(size_t)gy * Nn + gx] = xb[(size_t)gy * Nn + gx] + acc[y][k];
                }
            }
        }
        return;
    }

    // ================= frame path (exact two-stage, 3-px border) ============
    const int seg = blockIdx.x - NINT;
    int oy0, ox0, OH, OW;
    if (seg < 8)       { oy0 = 0;    OH = 3; ox0 = seg * 128;        OW = 128; }
    else if (seg < 16) { oy0 = 1021; OH = 3; ox0 = (seg - 8) * 128;  OW = 128; }
    else if (seg < 24) { ox0 = 0;    OW = 3; oy0 = 3 + (seg - 16) * 128; OH = min(128, 1021 - oy0); }
    else               { ox0 = 1021; OW = 3; oy0 = 3 + (seg - 24) * 128; OH = min(128, 1021 - oy0); }
    const int TH = OH + 6,  TW = OW + 6;
    const int RH = OH + 12, RW = OW + 12;
    const int XH = OH + 14, XW = OW + 14;

    float* sx = smem + FOFF_SX;
    float* sr = smem + FOFF_SR;
    float* st = smem + FOFF_ST;
    float* sw1 = smem + FOFF_W1;
    float* sw2 = smem + FOFF_W2;
    float* skA = smem + FOFF_KA;

    if (tid < ODIM) { sw1[tid] = g_w1[b][tid]; sw2[tid] = g_w2[b][tid]; }
    if (tid < 9) skA[tid] = kA[b * 9 + tid];
    __syncthreads();

    for (int p = tid; p < XH * XW; p += 256) {
        int i = p / XW, j = p % XW;
        int gy = oy0 - 7 + i, gx = ox0 - 7 + j;
        sx[p] = (gy >= 0 && gy < Nn && gx >= 0 && gx < Nn) ? xb[gy * Nn + gx] : 0.f;
    }
    __syncthreads();

    for (int p = tid; p < RH * RW; p += 256) {
        int i = p / RW, j = p % RW;
        int gy = oy0 - 6 + i, gx = ox0 - 6 + j;
        float v = 0.f;
        if (gy >= 0 && gy < Nn && gx >= 0 && gx < Nn) {
            v = fb[gy * Nn + gx];
#pragma unroll
            for (int a = 0; a < 3; a++)
#pragma unroll
                for (int c = 0; c < 3; c++)
                    v -= skA[a * 3 + c] * sx[(i + a) * XW + (j + c)];
        }
        sr[p] = v;
    }
    __syncthreads();

    const int TA = TH * TW;
    for (int p = tid; p < 3 * TA; p += 256) {
        int m = p / TA, q = p - m * TA;
        int i = q / TW, j = q % TW;
        int gy = oy0 - 3 + i, gx = ox0 - 3 + j;
        float v = 0.f;
        if (gy >= 0 && gy < Nn && gx >= 0 && gx < Nn) {
#pragma unroll
            for (int a = 0; a < 7; a++)
#pragma unroll
                for (int c = 0; c < 7; c++)
                    v += sw1[m * 49 + a * 7 + c] * sr[(i + a) * RW + (j + c)];
        }
        st[m * TA + q] = v;
    }
    __syncthreads();

    for (int p = tid; p < OH * OW; p += 256) {
        int y = p / OW, xc = p % OW;
        float v = sx[(y + 7) * XW + (xc + 7)];
#pragma unroll
        for (int m = 0; m < MLc; m++)
#pragma unroll
            for (int a = 0; a < 7; a++)
#pragma unroll
                for (int c = 0; c < 7; c++)
                    v += sw2[m * 49 + a * 7 + c] * st[m * TA + (y + a) * TW + (xc + c)];
        ob[(oy0 + y) * Nn + (ox0 + xc)] = v;
    }
}

// ---------------------------------------------------------------------------
extern "C" void kernel_launch(void* const* d_in, const int* in_sizes, int n_in,
                              void* d_out, int out_size) {
    const float* x      = (const float*)d_in[0];
    const float* f      = (const float*)d_in[1];
    const float* kA     = (const float*)d_in[2];
    const float* fc1_w1 = (const float*)d_in[3];
    const float* fc1_b1 = (const float*)d_in[4];
    const float* fc1_w2 = (const float*)d_in[5];
    const float* fc1_b2 = (const float*)d_in[6];
    const float* fc2_w1 = (const float*)d_in[7];
    const float* fc2_b1 = (const float*)d_in[8];
    const float* fc2_w2 = (const float*)d_in[9];
    const float* fc2_b2 = (const float*)d_in[10];
    float* out = (float*)d_out;

    cudaFuncSetAttribute(fused_kernel,
                         cudaFuncAttributeMaxDynamicSharedMemorySize, SMEM_BYTES);

    mlp_kernel<<<Bn, 768>>>(kA, fc1_w1, fc1_b1, fc1_w2, fc1_b2,
                            fc2_w1, fc2_b1, fc2_w2, fc2_b2);

    dim3 g(NINT + 32, Bn);
    fused_kernel<<<g, 256, SMEM_BYTES>>>(x, f, kA, out);
}